// round 8
// baseline (speedup 1.0000x reference)
#include <cuda_runtime.h>
#include <math.h>

// Problem constants
#define Bb 16
#define Tt 16
#define Cc 64
#define HD 64
#define HW 1024
#define IMW 32
#define NT 128
#define SROW 36
#define PLANE (34*SROW)   // 1224 floats per padded plane

typedef unsigned long long ull;

// Scratch (device globals: no allocation allowed)
__device__ float g_h   [Bb*HD*HW];
__device__ float g_hode[Bb*HD*HW];
__device__ float g_rh  [Bb*HD*HW];
__device__ float g_u   [Bb*HD*HW];
__device__ float g_gx  [(size_t)Tt*Bb*2*HD*HW];   // x-part of gates conv (+bias)
__device__ float g_cx  [(size_t)Tt*Bb*HD*HW];     // x-part of cand conv (+bias)

// ---- packed f32x2 helpers ----
__device__ __forceinline__ ull pk2(float lo, float hi) {
    ull r; asm("mov.b64 %0, {%1, %2};" : "=l"(r) : "f"(lo), "f"(hi)); return r;
}
__device__ __forceinline__ ull fma2(ull a, ull b, ull c) {
    ull d; asm("fma.rn.f32x2 %0, %1, %2, %3;" : "=l"(d) : "l"(a), "l"(b), "l"(c)); return d;
}
__device__ __forceinline__ float lo2(ull v) { return __uint_as_float((unsigned)v); }
__device__ __forceinline__ float hi2(ull v) { return __uint_as_float((unsigned)(v >> 32)); }

// ---------------------------------------------------------------------------
// Core: 3x3 SAME conv over 64 input channels, one 32x32 image, 4 output
// channels per CTA, 8 px/thread as 4 f32x2 pairs (128 threads). Two input
// channels per barrier; 4 smem planes (paired double buffer), zeroed borders.
// Patch row loads stay aligned (2xLDS.128 + LDS.64); only the middle tap
// needs 4 odd-pair packs per row. Weights staged as duplicated (w,w) pairs,
// layout ws2[((ci*3 + r)*4 + oc)*4 + tap] (3 real taps + pad, 32B slots).
// smem = 3072 pairs (24576 B) + 4*PLANE floats (19584 B) = 44160 B.
// ---------------------------------------------------------------------------
__device__ __forceinline__ void conv_core64(
    const float* __restrict__ in,     // [64][1024]
    const float* __restrict__ wsrc,   // per-oc row stride = wstride9 floats
    int wstride9, int ocb,
    ull acc2[4][4])
{
    extern __shared__ float smem[];
    ull*   ws2 = reinterpret_cast<ull*>(smem);    // 3072 pairs
    float* pl  = smem + 6144;                     // 4*PLANE floats
    const int tid = threadIdx.x;
    const int row = tid >> 2;          // 0..31
    const int xb  = (tid & 3) << 3;    // 0,8,16,24

    // Stage duplicated weight pairs
    for (int i = tid; i < 3072; i += NT) {
        const int tap = i & 3;
        const int oc_ = (i >> 2) & 3;
        const int r_  = (i >> 4) % 3;
        const int ci_ = i / 48;
        float v = 0.f;
        if (tap < 3)
            v = wsrc[(size_t)(ocb*4 + oc_)*wstride9 + ci_*9 + r_*3 + tap];
        ws2[i] = pk2(v, v);
    }
    for (int i = tid; i < 4*PLANE; i += NT) pl[i] = 0.f;

    const int goff = row*IMW + xb;
    float4 n0a = *reinterpret_cast<const float4*>(in + goff);
    float4 n0b = *reinterpret_cast<const float4*>(in + goff + 4);
    float4 n1a = *reinterpret_cast<const float4*>(in + HW + goff);
    float4 n1b = *reinterpret_cast<const float4*>(in + HW + goff + 4);
    __syncthreads();   // zero/weights visible before interior stores

    #pragma unroll 1
    for (int pr = 0; pr < 32; pr++) {
        float* b0 = pl + (pr & 1)*2*PLANE;
        float* b1 = b0 + PLANE;
        {
            float* d0 = b0 + (row + 1)*SROW + xb + 1;
            d0[0]=n0a.x; d0[1]=n0a.y; d0[2]=n0a.z; d0[3]=n0a.w;
            d0[4]=n0b.x; d0[5]=n0b.y; d0[6]=n0b.z; d0[7]=n0b.w;
            float* d1 = b1 + (row + 1)*SROW + xb + 1;
            d1[0]=n1a.x; d1[1]=n1a.y; d1[2]=n1a.z; d1[3]=n1a.w;
            d1[4]=n1b.x; d1[5]=n1b.y; d1[6]=n1b.z; d1[7]=n1b.w;
        }
        __syncthreads();
        if (pr < 31) {
            const float* g = in + (2*pr + 2)*HW + goff;
            n0a = *reinterpret_cast<const float4*>(g);
            n0b = *reinterpret_cast<const float4*>(g + 4);
            n1a = *reinterpret_cast<const float4*>(g + HW);
            n1b = *reinterpret_cast<const float4*>(g + HW + 4);
        }
        #pragma unroll
        for (int half = 0; half < 2; half++) {
            const float* cur = half ? b1 : b0;
            const int ci = 2*pr + half;
            #pragma unroll
            for (int r = 0; r < 3; r++) {
                const ull* s = reinterpret_cast<const ull*>(cur + (row + r)*SROW + xb);
                ulonglong2 e01 = *reinterpret_cast<const ulonglong2*>(s);      // E0,E1
                ulonglong2 e23 = *reinterpret_cast<const ulonglong2*>(s + 2);  // E2,E3
                ull e4 = s[4];                                                 // E4
                ull O0 = pk2(hi2(e01.x), lo2(e01.y));
                ull O1 = pk2(hi2(e01.y), lo2(e23.x));
                ull O2 = pk2(hi2(e23.x), lo2(e23.y));
                ull O3 = pk2(hi2(e23.y), lo2(e4));
                const ull* wbase = ws2 + (size_t)((ci*3 + r)*4)*4;
                #pragma unroll
                for (int oc = 0; oc < 4; oc++) {
                    ulonglong2 w01 = *reinterpret_cast<const ulonglong2*>(wbase + oc*4);
                    ull w2p = wbase[oc*4 + 2];
                    acc2[oc][0] = fma2(e01.x, w01.x, fma2(O0, w01.y, fma2(e01.y, w2p, acc2[oc][0])));
                    acc2[oc][1] = fma2(e01.y, w01.x, fma2(O1, w01.y, fma2(e23.x, w2p, acc2[oc][1])));
                    acc2[oc][2] = fma2(e23.x, w01.x, fma2(O2, w01.y, fma2(e23.y, w2p, acc2[oc][2])));
                    acc2[oc][3] = fma2(e23.y, w01.x, fma2(O3, w01.y, fma2(e4,   w2p, acc2[oc][3])));
                }
            }
        }
    }
}

__device__ __forceinline__ float sigmoidf_(float x) { return 1.f / (1.f + expf(-x)); }

__device__ __forceinline__ void st8(float* o, const float a[8]) {
    *reinterpret_cast<float4*>(o)     = make_float4(a[0],a[1],a[2],a[3]);
    *reinterpret_cast<float4*>(o + 4) = make_float4(a[4],a[5],a[6],a[7]);
}
__device__ __forceinline__ void unpack8(const ull p[4], float a[8]) {
    #pragma unroll
    for (int j = 0; j < 4; j++) { a[2*j] = lo2(p[j]); a[2*j+1] = hi2(p[j]); }
}

// ---------------------------------------------------------------------------
// Precompute x-contributions: out[t][b][co][pix] = conv(x_{T-1-t}) + bias
// grid = (cout/4, T*B)
// ---------------------------------------------------------------------------
__global__ void __launch_bounds__(NT) k_pre(
    const float* __restrict__ x0, const float* __restrict__ w, int wstride9,
    const float* __restrict__ bias, float* __restrict__ out, int cout)
{
    const int ocb = blockIdx.x, z = blockIdx.y;
    const int t = z >> 4, b = z & 15;
    const float* in = x0 + ((size_t)(b*Tt + (Tt-1-t))*Cc)*HW;

    ull acc2[4][4];
    #pragma unroll
    for (int oc = 0; oc < 4; oc++) {
        ull bv = pk2(bias[ocb*4 + oc], bias[ocb*4 + oc]);
        #pragma unroll
        for (int j = 0; j < 4; j++) acc2[oc][j] = bv;
    }
    conv_core64(in, w, wstride9, ocb, acc2);

    const int row = threadIdx.x >> 2, xb = (threadIdx.x & 3) << 3;
    float* o = out + ((size_t)(t*Bb + b)*cout + ocb*4)*HW + row*IMW + xb;
    #pragma unroll
    for (int oc = 0; oc < 4; oc++) {
        float a[8]; unpack8(acc2[oc], a);
        st8(o + oc*HW, a);
    }
}

// ---------------------------------------------------------------------------
// ODE: h_ode = h + tanh(conv(h)+b)*dt   grid = (16, B)
// ---------------------------------------------------------------------------
__global__ void __launch_bounds__(NT) k_ode(
    const float* __restrict__ w, const float* __restrict__ bias,
    const float* __restrict__ ts, int step)
{
    const int ocb = blockIdx.x, b = blockIdx.y;
    const float* in = g_h + (size_t)b*HD*HW;

    ull acc2[4][4];
    #pragma unroll
    for (int oc = 0; oc < 4; oc++) {
        ull bv = pk2(bias[ocb*4 + oc], bias[ocb*4 + oc]);
        #pragma unroll
        for (int j = 0; j < 4; j++) acc2[oc][j] = bv;
    }
    conv_core64(in, w, 576, ocb, acc2);

    const float dt = (step == 0) ? -0.01f : (ts[Tt-1-step] - ts[Tt-step]);
    const int row = threadIdx.x >> 2, xb = (threadIdx.x & 3) << 3;
    #pragma unroll
    for (int oc = 0; oc < 4; oc++) {
        size_t ib = ((size_t)b*HD + ocb*4 + oc)*HW + row*IMW + xb;
        float a[8]; unpack8(acc2[oc], a);
        float r[8];
        #pragma unroll
        for (int px = 0; px < 8; px++)
            r[px] = g_h[ib + px] + tanhf(a[px])*dt;
        st8(&g_hode[ib], r);
    }
}

// ---------------------------------------------------------------------------
// Gates: g = sigmoid(conv(h_ode)+gx).  co<64 -> rh = g*h_ode; else u = g.
// grid = (32, B)
// ---------------------------------------------------------------------------
__global__ void __launch_bounds__(NT) k_gates(const float* __restrict__ w, int step)
{
    const int ocb = blockIdx.x, b = blockIdx.y;
    const float* in = g_hode + (size_t)b*HD*HW;

    ull acc2[4][4];
    #pragma unroll
    for (int oc = 0; oc < 4; oc++)
        #pragma unroll
        for (int j = 0; j < 4; j++) acc2[oc][j] = 0ull;
    conv_core64(in, w, 1152, ocb, acc2);

    const int row = threadIdx.x >> 2, xb = (threadIdx.x & 3) << 3;
    const int co0 = ocb*4;
    const float* pre = g_gx + ((size_t)(step*Bb + b)*(2*HD) + co0)*HW + row*IMW + xb;
    #pragma unroll
    for (int oc = 0; oc < 4; oc++) {
        float a[8]; unpack8(acc2[oc], a);
        float g[8];
        #pragma unroll
        for (int px = 0; px < 8; px++)
            g[px] = sigmoidf_(a[px] + pre[oc*HW + px]);
        if (co0 < HD) {
            size_t ib = ((size_t)b*HD + co0 + oc)*HW + row*IMW + xb;
            #pragma unroll
            for (int px = 0; px < 8; px++) g[px] *= g_hode[ib + px];
            st8(&g_rh[ib], g);
        } else {
            size_t ib = ((size_t)b*HD + co0 - HD + oc)*HW + row*IMW + xb;
            st8(&g_u[ib], g);
        }
    }
}

// ---------------------------------------------------------------------------
// Candidate + GRU update + mask. grid = (16, B)
// ---------------------------------------------------------------------------
__global__ void __launch_bounds__(NT) k_cand(
    const float* __restrict__ w, const float* __restrict__ mask, int step)
{
    const int ocb = blockIdx.x, b = blockIdx.y;
    const float* in = g_rh + (size_t)b*HD*HW;

    ull acc2[4][4];
    #pragma unroll
    for (int oc = 0; oc < 4; oc++)
        #pragma unroll
        for (int j = 0; j < 4; j++) acc2[oc][j] = 0ull;
    conv_core64(in, w, 1152, ocb, acc2);

    const float m = mask[b*Tt + (Tt-1-step)];
    const int row = threadIdx.x >> 2, xb = (threadIdx.x & 3) << 3;
    const float* pre = g_cx + ((size_t)(step*Bb + b)*HD + ocb*4)*HW + row*IMW + xb;
    #pragma unroll
    for (int oc = 0; oc < 4; oc++) {
        size_t ib = ((size_t)b*HD + ocb*4 + oc)*HW + row*IMW + xb;
        float a[8]; unpack8(acc2[oc], a);
        float r[8];
        #pragma unroll
        for (int px = 0; px < 8; px++) {
            float ho = g_hode[ib + px];
            float c  = tanhf(a[px] + pre[oc*HW + px]);
            r[px] = ho + m*g_u[ib + px]*(c - ho);
        }
        st8(&g_h[ib], r);
    }
}

// ---------------------------------------------------------------------------
// Head: z1 = relu(W1 h + b1); z2 = W2 z1 + b2; out = [z2[:64] ; |z2[64:]|]
// grid = (4, B)
// ---------------------------------------------------------------------------
__global__ void __launch_bounds__(256) k_final(
    const float* __restrict__ w1, const float* __restrict__ b1,
    const float* __restrict__ w2, const float* __restrict__ b2,
    float* __restrict__ out)
{
    extern __shared__ float smem[];
    float* w1s = smem;          // [64][64]
    float* w2s = smem + 4096;   // [128][64]
    const int tid = threadIdx.x, pb = blockIdx.x, b = blockIdx.y;
    for (int i = tid; i < 4096; i += 256) w1s[i] = w1[i];
    for (int i = tid; i < 8192; i += 256) w2s[i] = w2[i];
    __syncthreads();

    const int pix = pb*256 + tid;
    float z1[64];
    #pragma unroll
    for (int co = 0; co < 64; co++) z1[co] = b1[co];
    for (int ci = 0; ci < 64; ci++) {
        float hv = g_h[((size_t)b*HD + ci)*HW + pix];
        #pragma unroll
        for (int co = 0; co < 64; co++) z1[co] += w1s[co*64 + ci]*hv;
    }
    #pragma unroll
    for (int co = 0; co < 64; co++) z1[co] = fmaxf(z1[co], 0.f);

    for (int co2 = 0; co2 < 128; co2++) {
        float a = b2[co2];
        #pragma unroll
        for (int ci = 0; ci < 64; ci++) a += w2s[co2*64 + ci]*z1[ci];
        if (co2 < 64)
            out[((size_t)b*HD + co2)*HW + pix] = a;
        else
            out[(size_t)Bb*HD*HW + ((size_t)b*HD + (co2 - 64))*HW + pix] = fabsf(a);
    }
}

// ---------------------------------------------------------------------------
extern "C" void kernel_launch(void* const* d_in, const int* in_sizes, int n_in,
                              void* d_out, int out_size)
{
    const float* input   = (const float*)d_in[0];
    const float* ts      = (const float*)d_in[1];
    const float* mask    = (const float*)d_in[2];
    const float* w_gates = (const float*)d_in[3];
    const float* b_gates = (const float*)d_in[4];
    const float* w_can   = (const float*)d_in[5];
    const float* b_can   = (const float*)d_in[6];
    const float* w_ode   = (const float*)d_in[7];
    const float* b_ode   = (const float*)d_in[8];
    const float* w_t1    = (const float*)d_in[9];
    const float* b_t1    = (const float*)d_in[10];
    const float* w_t2    = (const float*)d_in[11];
    const float* b_t2    = (const float*)d_in[12];
    float* out = (float*)d_out;

    float *hptr, *gxp, *cxp;
    cudaGetSymbolAddress((void**)&hptr, g_h);
    cudaGetSymbolAddress((void**)&gxp,  g_gx);
    cudaGetSymbolAddress((void**)&cxp,  g_cx);

    cudaMemsetAsync(hptr, 0, (size_t)Bb*HD*HW*sizeof(float));

    const int CSM = 3072*8 + 4*PLANE*4;   // 44160 B

    k_pre<<<dim3(32, Tt*Bb), NT, CSM>>>(input, w_gates, 1152, b_gates, gxp, 2*HD);
    k_pre<<<dim3(16, Tt*Bb), NT, CSM>>>(input, w_can,   1152, b_can,   cxp, HD);

    for (int s = 0; s < Tt; s++) {
        k_ode  <<<dim3(16, Bb), NT, CSM>>>(w_ode, b_ode, ts, s);
        k_gates<<<dim3(32, Bb), NT, CSM>>>(w_gates + 64*9, s);
        k_cand <<<dim3(16, Bb), NT, CSM>>>(w_can   + 64*9, mask, s);
    }

    k_final<<<dim3(4, Bb), 256, 12288*(int)sizeof(float)>>>(w_t1, b_t1, w_t2, b_t2, out);
}

// round 10
// speedup vs baseline: 1.2362x; 1.2362x over previous
#include <cuda_runtime.h>
#include <cuda_bf16.h>
#include <math.h>
#include <stdint.h>

// Problem constants
#define Bb 16
#define Tt 16
#define Cc 64
#define HD 64
#define HW 1024
#define IMW 32

// Scratch (device globals: no allocation allowed)
__device__ float g_h   [Bb*HD*HW];
__device__ float g_hode[Bb*HD*HW];
__device__ float g_rh  [Bb*HD*HW];
__device__ float g_u   [Bb*HD*HW];
__device__ float g_gx  [(size_t)Tt*Bb*2*HD*HW];   // x-part of gates conv (+bias)
__device__ float g_cx  [(size_t)Tt*Bb*HD*HW];     // x-part of cand conv (+bias)
// Pre-split weights, bf16 bits: [hl][row][k], k = tap*64 + ci
// rows: 0 ode | 64 gates_h(128) | 192 cand_h | 256 gates_x(128) | 384 cand_x
__device__ __align__(16) unsigned short g_Bw[2][448][576];

// Slab layout: [216 rc][70 ci-stride] bf16 halves (rc = r*36 + c)
#define SLAB_STR 70
#define SLABH    (216*SLAB_STR)    // 15120 halves
#define BSTR     68                // B row stride in halves
#define BH       (64*BSTR)         // 4352 halves
#define SMEMB    ((2*SLABH + 2*BH)*2)   // 77888 bytes

// bf16 m16n8k16 MMA (standard PTX, sm_80+; runs on sm_100 base target)
__device__ __forceinline__ void mma16816(float* c, const unsigned* a,
                                         unsigned b0, unsigned b1) {
    asm volatile(
        "mma.sync.aligned.m16n8k16.row.col.f32.bf16.bf16.f32 "
        "{%0,%1,%2,%3}, {%4,%5,%6,%7}, {%8,%9}, {%0,%1,%2,%3};\n"
        : "+f"(c[0]), "+f"(c[1]), "+f"(c[2]), "+f"(c[3])
        : "r"(a[0]), "r"(a[1]), "r"(a[2]), "r"(a[3]), "r"(b0), "r"(b1));
}

__device__ __forceinline__ float sigmoidf_(float x) { return 1.f / (1.f + expf(-x)); }

// ===========================================================================
// Weight pre-split: fp32 -> bf16 hi/lo, layout [hl][row][tap*64+ci]
// ===========================================================================
__global__ void k_wsplit(const float* __restrict__ w_ode,
                         const float* __restrict__ w_gates,
                         const float* __restrict__ w_can)
{
    int idx = blockIdx.x*256 + threadIdx.x;     // 448*576 = 258048
    if (idx >= 448*576) return;
    int r = idx / 576, k = idx % 576;
    int tap = k >> 6, ci = k & 63;

    float v;
    if      (r < 64)  v = w_ode  [ r       *576  + ci*9      + tap];
    else if (r < 192) v = w_gates[(r-64)   *1152 + (64+ci)*9 + tap];
    else if (r < 256) v = w_can  [(r-192)  *1152 + (64+ci)*9 + tap];
    else if (r < 384) v = w_gates[(r-256)  *1152 + ci*9      + tap];
    else              v = w_can  [(r-384)  *1152 + ci*9      + tap];

    __nv_bfloat16 h = __float2bfloat16_rn(v);
    __nv_bfloat16 l = __float2bfloat16_rn(v - __bfloat162float(h));
    g_Bw[0][r][k] = __bfloat16_as_ushort(h);
    g_Bw[1][r][k] = __bfloat16_as_ushort(l);
}

// ===========================================================================
// Unified conv-as-GEMM kernel. 128 threads (4 warps). CTA computes one
// [128 px x 64 oc] tile: grid = (8 tiles, nimg, nhalf).
// MODE: 0=ODE 1=GATES 2=CAND 3=PRE_GATES 4=PRE_CAND
// ===========================================================================
template<int MODE>
__global__ void __launch_bounds__(128) k_conv(
    const float* __restrict__ x0, const float* __restrict__ ts,
    const float* __restrict__ mask, const float* __restrict__ b_ode,
    const float* __restrict__ b_gates, const float* __restrict__ b_can,
    int step)
{
    extern __shared__ unsigned short sm2[];
    unsigned short* slab_hi = sm2;
    unsigned short* slab_lo = sm2 + SLABH;
    unsigned short* Bs_hi   = sm2 + 2*SLABH;
    unsigned short* Bs_lo   = sm2 + 2*SLABH + BH;

    const int tid  = threadIdx.x;
    const int w    = tid >> 5, lane = tid & 31;
    const int gid  = lane >> 2, tg = lane & 3;
    const int tile = blockIdx.x;
    const int img  = blockIdx.y;
    const int nh   = blockIdx.z;
    const int tile4 = tile*4;

    // Input image base
    const float* in;
    if (MODE >= 3) {
        int t = img >> 4, b = img & 15;
        in = x0 + ((size_t)(b*Tt + (Tt-1-t))*Cc)*HW;
    } else {
        in = (MODE == 0 ? g_h : (MODE == 1 ? g_hode : g_rh)) + (size_t)img*HD*HW;
    }

    // B row offset within g_Bw
    const int rowoff = (MODE == 0) ? 0
                     : (MODE == 1) ? 64 + nh*64
                     : (MODE == 2) ? 192
                     : (MODE == 3) ? 256 + nh*64
                     : 384;

    // ---- Build bf16 hi/lo slabs: region rows tile4-1..tile4+4, cols -1..34 ----
    for (int i = tid; i < 216*64; i += 128) {
        int ci = i / 216, rc = i - ci*216;
        int rr = rc / 36, cc = rc - rr*36;
        int ir = tile4 + rr - 1, ic = cc - 1;
        float v = 0.f;
        if ((unsigned)ir < 32u && (unsigned)ic < 32u)
            v = in[ci*HW + ir*IMW + ic];
        __nv_bfloat16 h = __float2bfloat16_rn(v);
        __nv_bfloat16 l = __float2bfloat16_rn(v - __bfloat162float(h));
        slab_hi[rc*SLAB_STR + ci] = __bfloat16_as_ushort(h);
        slab_lo[rc*SLAB_STR + ci] = __bfloat16_as_ushort(l);
    }

    float acc[2][8][4];
    #pragma unroll
    for (int mt = 0; mt < 2; mt++)
        #pragma unroll
        for (int nt = 0; nt < 8; nt++)
            #pragma unroll
            for (int e = 0; e < 4; e++) acc[mt][nt][e] = 0.f;

    // ---- Main loop over 9 taps ----
    #pragma unroll 1
    for (int tap = 0; tap < 9; tap++) {
        __syncthreads();   // prior-tap B reads done (also covers slab build on tap 0)
        // Stage B chunk (64 rows x 64 k bf16) for hi and lo
        for (int i = tid; i < 1024; i += 128) {
            int n = i >> 4, q = i & 15;
            const uint2* sh = reinterpret_cast<const uint2*>(&g_Bw[0][rowoff + n][tap*64]) + q;
            const uint2* sl = reinterpret_cast<const uint2*>(&g_Bw[1][rowoff + n][tap*64]) + q;
            *reinterpret_cast<uint2*>(reinterpret_cast<char*>(Bs_hi) + n*(BSTR*2) + q*8) = *sh;
            *reinterpret_cast<uint2*>(reinterpret_cast<char*>(Bs_lo) + n*(BSTR*2) + q*8) = *sl;
        }
        __syncthreads();

        const int tr = tap/3, tc = tap - tr*3;
        const int rs = w + tr;   // slab row for this warp's 32-px block
        const unsigned short* shb = slab_hi + (rs*36 + tc)*SLAB_STR;
        const unsigned short* slb = slab_lo + (rs*36 + tc)*SLAB_STR;

        #pragma unroll
        for (int kq = 0; kq < 4; kq++) {
            const int kk = kq*16 + tg*2;
            unsigned ah[2][4], al[2][4];
            #pragma unroll
            for (int mt = 0; mt < 2; mt++) {
                const unsigned short* p = shb + (mt*16 + gid)*SLAB_STR + kk;
                ah[mt][0] = *reinterpret_cast<const unsigned*>(p);
                ah[mt][1] = *reinterpret_cast<const unsigned*>(p + 8*SLAB_STR);
                ah[mt][2] = *reinterpret_cast<const unsigned*>(p + 8);
                ah[mt][3] = *reinterpret_cast<const unsigned*>(p + 8*SLAB_STR + 8);
                const unsigned short* q = slb + (mt*16 + gid)*SLAB_STR + kk;
                al[mt][0] = *reinterpret_cast<const unsigned*>(q);
                al[mt][1] = *reinterpret_cast<const unsigned*>(q + 8*SLAB_STR);
                al[mt][2] = *reinterpret_cast<const unsigned*>(q + 8);
                al[mt][3] = *reinterpret_cast<const unsigned*>(q + 8*SLAB_STR + 8);
            }
            #pragma unroll
            for (int nt = 0; nt < 8; nt++) {
                const unsigned short* pb = Bs_hi + (nt*8 + gid)*BSTR + kk;
                unsigned bh0 = *reinterpret_cast<const unsigned*>(pb);
                unsigned bh1 = *reinterpret_cast<const unsigned*>(pb + 8);
                const unsigned short* pl = Bs_lo + (nt*8 + gid)*BSTR + kk;
                unsigned bl0 = *reinterpret_cast<const unsigned*>(pl);
                unsigned bl1 = *reinterpret_cast<const unsigned*>(pl + 8);
                #pragma unroll
                for (int mt = 0; mt < 2; mt++) {
                    mma16816(acc[mt][nt], ah[mt], bh0, bh1);
                    mma16816(acc[mt][nt], al[mt], bh0, bh1);
                    mma16816(acc[mt][nt], ah[mt], bl0, bl1);
                }
            }
        }
    }

    // ---- Epilogue (thread owns 64 (px,oc) values) ----
    const int pxb = tile*128 + w*32;
    float dt = 0.f, m = 0.f;
    if (MODE == 0) dt = (step == 0) ? -0.01f : (ts[Tt-1-step] - ts[Tt-step]);
    if (MODE == 2) m  = mask[img*Tt + (Tt-1-step)];

    #pragma unroll
    for (int mt = 0; mt < 2; mt++) {
        #pragma unroll
        for (int nt = 0; nt < 8; nt++) {
            const int ocb = nt*8 + tg*2;
            const int px0 = pxb + mt*16 + gid;
            #pragma unroll
            for (int e = 0; e < 4; e++) {
                const int px = px0 + (e >> 1)*8;
                const int oc = ocb + (e & 1);
                float v = acc[mt][nt][e];
                if (MODE == 0) {
                    size_t ib = (size_t)img*HD*HW + (size_t)oc*HW + px;
                    g_hode[ib] = g_h[ib] + tanhf(v + b_ode[oc])*dt;
                } else if (MODE == 1) {
                    float gx = g_gx[((size_t)(step*Bb + img)*(2*HD) + nh*64 + oc)*HW + px];
                    float g = sigmoidf_(v + gx);
                    size_t ib = (size_t)img*HD*HW + (size_t)oc*HW + px;
                    if (nh == 0) g_rh[ib] = g * g_hode[ib];
                    else         g_u[ib]  = g;
                } else if (MODE == 2) {
                    float cx = g_cx[((size_t)(step*Bb + img)*HD + oc)*HW + px];
                    size_t ib = (size_t)img*HD*HW + (size_t)oc*HW + px;
                    float ho = g_hode[ib];
                    g_h[ib] = ho + m*g_u[ib]*(tanhf(v + cx) - ho);
                } else if (MODE == 3) {
                    g_gx[((size_t)img*(2*HD) + nh*64 + oc)*HW + px] = v + b_gates[nh*64 + oc];
                } else {
                    g_cx[((size_t)img*HD + oc)*HW + px] = v + b_can[oc];
                }
            }
        }
    }
}

// ===========================================================================
// Head: z1 = relu(W1 h + b1); z2 = W2 z1 + b2; out = [z2[:64] ; |z2[64:]|]
// ===========================================================================
__global__ void __launch_bounds__(256) k_final(
    const float* __restrict__ w1, const float* __restrict__ b1,
    const float* __restrict__ w2, const float* __restrict__ b2,
    float* __restrict__ out)
{
    extern __shared__ float smem[];
    float* w1s = smem;          // [64][64]
    float* w2s = smem + 4096;   // [128][64]
    const int tid = threadIdx.x, pb = blockIdx.x, b = blockIdx.y;
    for (int i = tid; i < 4096; i += 256) w1s[i] = w1[i];
    for (int i = tid; i < 8192; i += 256) w2s[i] = w2[i];
    __syncthreads();

    const int pix = pb*256 + tid;
    float z1[64];
    #pragma unroll
    for (int co = 0; co < 64; co++) z1[co] = b1[co];
    for (int ci = 0; ci < 64; ci++) {
        float hv = g_h[((size_t)b*HD + ci)*HW + pix];
        #pragma unroll
        for (int co = 0; co < 64; co++) z1[co] += w1s[co*64 + ci]*hv;
    }
    #pragma unroll
    for (int co = 0; co < 64; co++) z1[co] = fmaxf(z1[co], 0.f);

    for (int co2 = 0; co2 < 128; co2++) {
        float a = b2[co2];
        #pragma unroll
        for (int ci = 0; ci < 64; ci++) a += w2s[co2*64 + ci]*z1[ci];
        if (co2 < 64)
            out[((size_t)b*HD + co2)*HW + pix] = a;
        else
            out[(size_t)Bb*HD*HW + ((size_t)b*HD + (co2 - 64))*HW + pix] = fabsf(a);
    }
}

// ---------------------------------------------------------------------------
extern "C" void kernel_launch(void* const* d_in, const int* in_sizes, int n_in,
                              void* d_out, int out_size)
{
    const float* input   = (const float*)d_in[0];
    const float* ts      = (const float*)d_in[1];
    const float* mask    = (const float*)d_in[2];
    const float* w_gates = (const float*)d_in[3];
    const float* b_gates = (const float*)d_in[4];
    const float* w_can   = (const float*)d_in[5];
    const float* b_can   = (const float*)d_in[6];
    const float* w_ode   = (const float*)d_in[7];
    const float* b_ode   = (const float*)d_in[8];
    const float* w_t1    = (const float*)d_in[9];
    const float* b_t1    = (const float*)d_in[10];
    const float* w_t2    = (const float*)d_in[11];
    const float* b_t2    = (const float*)d_in[12];
    float* out = (float*)d_out;

    float* hptr;
    cudaGetSymbolAddress((void**)&hptr, g_h);

    cudaFuncSetAttribute(k_conv<0>, cudaFuncAttributeMaxDynamicSharedMemorySize, SMEMB);
    cudaFuncSetAttribute(k_conv<1>, cudaFuncAttributeMaxDynamicSharedMemorySize, SMEMB);
    cudaFuncSetAttribute(k_conv<2>, cudaFuncAttributeMaxDynamicSharedMemorySize, SMEMB);
    cudaFuncSetAttribute(k_conv<3>, cudaFuncAttributeMaxDynamicSharedMemorySize, SMEMB);
    cudaFuncSetAttribute(k_conv<4>, cudaFuncAttributeMaxDynamicSharedMemorySize, SMEMB);

    cudaMemsetAsync(hptr, 0, (size_t)Bb*HD*HW*sizeof(float));
    k_wsplit<<<1008, 256>>>(w_ode, w_gates, w_can);

    // Precompute x-contributions for all T steps (tensor-core path)
    k_conv<3><<<dim3(8, Tt*Bb, 2), 128, SMEMB>>>(input, ts, mask, b_ode, b_gates, b_can, 0);
    k_conv<4><<<dim3(8, Tt*Bb, 1), 128, SMEMB>>>(input, ts, mask, b_ode, b_gates, b_can, 0);

    // Sequential scan
    for (int s = 0; s < Tt; s++) {
        k_conv<0><<<dim3(8, Bb, 1), 128, SMEMB>>>(input, ts, mask, b_ode, b_gates, b_can, s);
        k_conv<1><<<dim3(8, Bb, 2), 128, SMEMB>>>(input, ts, mask, b_ode, b_gates, b_can, s);
        k_conv<2><<<dim3(8, Bb, 1), 128, SMEMB>>>(input, ts, mask, b_ode, b_gates, b_can, s);
    }

    k_final<<<dim3(4, Bb), 256, 12288*(int)sizeof(float)>>>(w_t1, b_t1, w_t2, b_t2, out);
}

// round 11
// speedup vs baseline: 1.4229x; 1.1511x over previous
#include <cuda_runtime.h>
#include <cuda_bf16.h>
#include <math.h>
#include <stdint.h>

// Problem constants
#define Bb 16
#define Tt 16
#define Cc 64
#define HD 64
#define HW 1024
#define IMW 32

// Scratch (device globals: no allocation allowed)
__device__ float g_h   [Bb*HD*HW];
__device__ float g_hode[Bb*HD*HW];
__device__ float g_rh  [Bb*HD*HW];
__device__ float g_u   [Bb*HD*HW];
__device__ float g_gx  [(size_t)Tt*Bb*2*HD*HW];   // x-part of gates conv (+bias)
__device__ float g_cx  [(size_t)Tt*Bb*HD*HW];     // x-part of cand conv (+bias)
// Pre-split weights, bf16 bits: [hl][row][k], k = tap*64 + ci
// rows: 0 ode | 64 gates_h(128) | 192 cand_h | 256 gates_x(128) | 384 cand_x
__device__ __align__(16) unsigned short g_Bw[2][448][576];

// Smem layout (halves): slab stride 72 (64 ci + pad), 144 rc rows (4x36);
// B stride 72, 64 rows.
#define SLAB_STR 72
#define SLAB_RC  144
#define SLABH    (SLAB_RC*SLAB_STR)   // 10368
#define BSTR     72
#define BH       (64*BSTR)            // 4608
#define SMEMB    ((2*SLABH + 2*BH)*2) // 59904 bytes

// bf16 m16n8k16 MMA (standard PTX, sm_80+)
__device__ __forceinline__ void mma16816(float* c, const unsigned* a,
                                         unsigned b0, unsigned b1) {
    asm volatile(
        "mma.sync.aligned.m16n8k16.row.col.f32.bf16.bf16.f32 "
        "{%0,%1,%2,%3}, {%4,%5,%6,%7}, {%8,%9}, {%0,%1,%2,%3};\n"
        : "+f"(c[0]), "+f"(c[1]), "+f"(c[2]), "+f"(c[3])
        : "r"(a[0]), "r"(a[1]), "r"(a[2]), "r"(a[3]), "r"(b0), "r"(b1));
}
__device__ __forceinline__ void ldsm_x4(unsigned* r, uint32_t addr) {
    asm volatile("ldmatrix.sync.aligned.m8n8.x4.shared.b16 {%0,%1,%2,%3}, [%4];"
        : "=r"(r[0]), "=r"(r[1]), "=r"(r[2]), "=r"(r[3]) : "r"(addr));
}
__device__ __forceinline__ float sigmoidf_(float x) { return 1.f / (1.f + expf(-x)); }

// ===========================================================================
// Weight pre-split: fp32 -> bf16 hi/lo, layout [hl][row][tap*64+ci]
// ===========================================================================
__global__ void k_wsplit(const float* __restrict__ w_ode,
                         const float* __restrict__ w_gates,
                         const float* __restrict__ w_can)
{
    int idx = blockIdx.x*256 + threadIdx.x;     // 448*576 = 258048
    if (idx >= 448*576) return;
    int r = idx / 576, k = idx % 576;
    int tap = k >> 6, ci = k & 63;

    float v;
    if      (r < 64)  v = w_ode  [ r       *576  + ci*9      + tap];
    else if (r < 192) v = w_gates[(r-64)   *1152 + (64+ci)*9 + tap];
    else if (r < 256) v = w_can  [(r-192)  *1152 + (64+ci)*9 + tap];
    else if (r < 384) v = w_gates[(r-256)  *1152 + ci*9      + tap];
    else              v = w_can  [(r-384)  *1152 + ci*9      + tap];

    __nv_bfloat16 h = __float2bfloat16_rn(v);
    __nv_bfloat16 l = __float2bfloat16_rn(v - __bfloat162float(h));
    g_Bw[0][r][k] = __bfloat16_as_ushort(h);
    g_Bw[1][r][k] = __bfloat16_as_ushort(l);
}

// ===========================================================================
// Conv-as-GEMM. CTA (128 thr, 4 warps) computes [64 px x 64 oc]:
// tile = 2 image rows. Warp w: px row (w>>1), cols (w&1)*16..+16, all 64 oc.
// grid = (16 tiles, nimg, nhalf). MODE: 0=ODE 1=GATES 2=CAND 3=PRE_G 4=PRE_C
// ===========================================================================
template<int MODE>
__global__ void __launch_bounds__(128) k_conv(
    const float* __restrict__ x0, const float* __restrict__ ts,
    const float* __restrict__ mask, const float* __restrict__ b_ode,
    const float* __restrict__ b_gates, const float* __restrict__ b_can,
    int step)
{
    extern __shared__ unsigned short sm2[];
    unsigned short* slab_hi = sm2;
    unsigned short* slab_lo = sm2 + SLABH;
    unsigned short* Bs_hi   = sm2 + 2*SLABH;
    unsigned short* Bs_lo   = sm2 + 2*SLABH + BH;

    const int tid  = threadIdx.x;
    const int w    = tid >> 5, lane = tid & 31;
    const int tile = blockIdx.x;
    const int img  = blockIdx.y;
    const int nh   = blockIdx.z;

    const float* in;
    if (MODE >= 3) {
        int t = img >> 4, b = img & 15;
        in = x0 + ((size_t)(b*Tt + (Tt-1-t))*Cc)*HW;
    } else {
        in = (MODE == 0 ? g_h : (MODE == 1 ? g_hode : g_rh)) + (size_t)img*HD*HW;
    }
    const int rowoff = (MODE == 0) ? 0
                     : (MODE == 1) ? 64 + nh*64
                     : (MODE == 2) ? 192
                     : (MODE == 3) ? 256 + nh*64
                     : 384;

    // ---- Build slabs: image rows tile*2-1 .. tile*2+2, cols -1..34 ----
    for (int i = tid; i < SLAB_RC*64; i += 128) {
        int ci = i / SLAB_RC, rc = i - ci*SLAB_RC;
        int rr = rc / 36, cc = rc - rr*36;
        int ir = tile*2 + rr - 1, ic = cc - 1;
        float v = 0.f;
        if ((unsigned)ir < 32u && (unsigned)ic < 32u)
            v = in[ci*HW + ir*IMW + ic];
        __nv_bfloat16 h = __float2bfloat16_rn(v);
        __nv_bfloat16 l = __float2bfloat16_rn(v - __bfloat162float(h));
        slab_hi[rc*SLAB_STR + ci] = __bfloat16_as_ushort(h);
        slab_lo[rc*SLAB_STR + ci] = __bfloat16_as_ushort(l);
    }

    const uint32_t slab_hi_u = (uint32_t)__cvta_generic_to_shared(slab_hi);
    const uint32_t slab_lo_u = (uint32_t)__cvta_generic_to_shared(slab_lo);
    const uint32_t bs_hi_u   = (uint32_t)__cvta_generic_to_shared(Bs_hi);
    const uint32_t bs_lo_u   = (uint32_t)__cvta_generic_to_shared(Bs_lo);

    float acc[8][4];
    #pragma unroll
    for (int nt = 0; nt < 8; nt++)
        #pragma unroll
        for (int e = 0; e < 4; e++) acc[nt][e] = 0.f;

    // B fragment smem offset (bytes), constant across taps except kq
    const uint32_t bfrag0 = (uint32_t)(((lane & 7) + ((lane >> 4) << 3))*BSTR*2)
                          + (((lane >> 3) & 1) << 4);

    #pragma unroll 1
    for (int tap = 0; tap < 9; tap++) {
        __syncthreads();   // prior-tap B reads done (tap0: slab stores visible)
        // Stage B chunk: 64 rows x 64 halves, hi+lo
        for (int i = tid; i < 512; i += 128) {
            int n = i >> 3, q = i & 7;
            *reinterpret_cast<uint4*>(reinterpret_cast<char*>(Bs_hi) + n*(BSTR*2) + q*16)
                = *(reinterpret_cast<const uint4*>(&g_Bw[0][rowoff + n][tap*64]) + q);
            *reinterpret_cast<uint4*>(reinterpret_cast<char*>(Bs_lo) + n*(BSTR*2) + q*16)
                = *(reinterpret_cast<const uint4*>(&g_Bw[1][rowoff + n][tap*64]) + q);
        }
        __syncthreads();

        const int tr = tap/3, tc = tap - tr*3;
        const int base_rc = ((w >> 1) + tr)*36 + (w & 1)*16 + tc;
        const uint32_t a_off = (uint32_t)((base_rc + (lane & 15))*SLAB_STR*2)
                             + ((lane >> 4) << 4);

        #pragma unroll
        for (int kq = 0; kq < 4; kq++) {
            unsigned ah[4], al[4];
            ldsm_x4(ah, slab_hi_u + a_off + kq*32);
            ldsm_x4(al, slab_lo_u + a_off + kq*32);
            #pragma unroll
            for (int ntp = 0; ntp < 4; ntp++) {
                unsigned bh[4], bl[4];
                const uint32_t boff = bfrag0 + (uint32_t)(ntp*16*BSTR*2) + kq*32;
                ldsm_x4(bh, bs_hi_u + boff);
                ldsm_x4(bl, bs_lo_u + boff);
                mma16816(acc[2*ntp],   ah, bh[0], bh[1]);
                mma16816(acc[2*ntp],   al, bh[0], bh[1]);
                mma16816(acc[2*ntp],   ah, bl[0], bl[1]);
                mma16816(acc[2*ntp+1], ah, bh[2], bh[3]);
                mma16816(acc[2*ntp+1], al, bh[2], bh[3]);
                mma16816(acc[2*ntp+1], ah, bl[2], bl[3]);
            }
        }
    }

    // ---- Epilogue ----
    const int row  = tile*2 + (w >> 1);
    const int colb = (w & 1)*16;
    float dt = 0.f, m = 0.f;
    if (MODE == 0) dt = (step == 0) ? -0.01f : (ts[Tt-1-step] - ts[Tt-step]);
    if (MODE == 2) m  = mask[img*Tt + (Tt-1-step)];

    #pragma unroll
    for (int nt = 0; nt < 8; nt++) {
        #pragma unroll
        for (int e = 0; e < 4; e++) {
            const int mm = (lane >> 2) + (e >> 1)*8;
            const int oc = nt*8 + (lane & 3)*2 + (e & 1);
            const int px = row*IMW + colb + mm;
            float v = acc[nt][e];
            if (MODE == 0) {
                size_t ib = (size_t)img*HD*HW + (size_t)oc*HW + px;
                g_hode[ib] = g_h[ib] + tanhf(v + b_ode[oc])*dt;
            } else if (MODE == 1) {
                float gx = g_gx[((size_t)(step*Bb + img)*(2*HD) + nh*64 + oc)*HW + px];
                float g = sigmoidf_(v + gx);
                size_t ib = (size_t)img*HD*HW + (size_t)oc*HW + px;
                if (nh == 0) g_rh[ib] = g * g_hode[ib];
                else         g_u[ib]  = g;
            } else if (MODE == 2) {
                float cx = g_cx[((size_t)(step*Bb + img)*HD + oc)*HW + px];
                size_t ib = (size_t)img*HD*HW + (size_t)oc*HW + px;
                float ho = g_hode[ib];
                g_h[ib] = ho + m*g_u[ib]*(tanhf(v + cx) - ho);
            } else if (MODE == 3) {
                g_gx[((size_t)img*(2*HD) + nh*64 + oc)*HW + px] = v + b_gates[nh*64 + oc];
            } else {
                g_cx[((size_t)img*HD + oc)*HW + px] = v + b_can[oc];
            }
        }
    }
}

// ===========================================================================
// Head: z1 = relu(W1 h + b1); z2 = W2 z1 + b2; out = [z2[:64] ; |z2[64:]|]
// ===========================================================================
__global__ void __launch_bounds__(256) k_final(
    const float* __restrict__ w1, const float* __restrict__ b1,
    const float* __restrict__ w2, const float* __restrict__ b2,
    float* __restrict__ out)
{
    extern __shared__ float smemf[];
    float* w1s = smemf;          // [64][64]
    float* w2s = smemf + 4096;   // [128][64]
    const int tid = threadIdx.x, pb = blockIdx.x, b = blockIdx.y;
    for (int i = tid; i < 4096; i += 256) w1s[i] = w1[i];
    for (int i = tid; i < 8192; i += 256) w2s[i] = w2[i];
    __syncthreads();

    const int pix = pb*256 + tid;
    float z1[64];
    #pragma unroll
    for (int co = 0; co < 64; co++) z1[co] = b1[co];
    for (int ci = 0; ci < 64; ci++) {
        float hv = g_h[((size_t)b*HD + ci)*HW + pix];
        #pragma unroll
        for (int co = 0; co < 64; co++) z1[co] += w1s[co*64 + ci]*hv;
    }
    #pragma unroll
    for (int co = 0; co < 64; co++) z1[co] = fmaxf(z1[co], 0.f);

    for (int co2 = 0; co2 < 128; co2++) {
        float a = b2[co2];
        #pragma unroll
        for (int ci = 0; ci < 64; ci++) a += w2s[co2*64 + ci]*z1[ci];
        if (co2 < 64)
            out[((size_t)b*HD + co2)*HW + pix] = a;
        else
            out[(size_t)Bb*HD*HW + ((size_t)b*HD + (co2 - 64))*HW + pix] = fabsf(a);
    }
}

// ---------------------------------------------------------------------------
extern "C" void kernel_launch(void* const* d_in, const int* in_sizes, int n_in,
                              void* d_out, int out_size)
{
    const float* input   = (const float*)d_in[0];
    const float* ts      = (const float*)d_in[1];
    const float* mask    = (const float*)d_in[2];
    const float* w_gates = (const float*)d_in[3];
    const float* b_gates = (const float*)d_in[4];
    const float* w_can   = (const float*)d_in[5];
    const float* b_can   = (const float*)d_in[6];
    const float* w_ode   = (const float*)d_in[7];
    const float* b_ode   = (const float*)d_in[8];
    const float* w_t1    = (const float*)d_in[9];
    const float* b_t1    = (const float*)d_in[10];
    const float* w_t2    = (const float*)d_in[11];
    const float* b_t2    = (const float*)d_in[12];
    float* out = (float*)d_out;

    float* hptr;
    cudaGetSymbolAddress((void**)&hptr, g_h);

    cudaFuncSetAttribute(k_conv<0>, cudaFuncAttributeMaxDynamicSharedMemorySize, SMEMB);
    cudaFuncSetAttribute(k_conv<1>, cudaFuncAttributeMaxDynamicSharedMemorySize, SMEMB);
    cudaFuncSetAttribute(k_conv<2>, cudaFuncAttributeMaxDynamicSharedMemorySize, SMEMB);
    cudaFuncSetAttribute(k_conv<3>, cudaFuncAttributeMaxDynamicSharedMemorySize, SMEMB);
    cudaFuncSetAttribute(k_conv<4>, cudaFuncAttributeMaxDynamicSharedMemorySize, SMEMB);

    cudaMemsetAsync(hptr, 0, (size_t)Bb*HD*HW*sizeof(float));
    k_wsplit<<<1008, 256>>>(w_ode, w_gates, w_can);

    // Precompute x-contributions for all T steps
    k_conv<3><<<dim3(16, Tt*Bb, 2), 128, SMEMB>>>(input, ts, mask, b_ode, b_gates, b_can, 0);
    k_conv<4><<<dim3(16, Tt*Bb, 1), 128, SMEMB>>>(input, ts, mask, b_ode, b_gates, b_can, 0);

    // Sequential scan
    for (int s = 0; s < Tt; s++) {
        k_conv<0><<<dim3(16, Bb, 1), 128, SMEMB>>>(input, ts, mask, b_ode, b_gates, b_can, s);
        k_conv<1><<<dim3(16, Bb, 2), 128, SMEMB>>>(input, ts, mask, b_ode, b_gates, b_can, s);
        k_conv<2><<<dim3(16, Bb, 1), 128, SMEMB>>>(input, ts, mask, b_ode, b_gates, b_can, s);
    }

    k_final<<<dim3(4, Bb), 256, 12288*(int)sizeof(float)>>>(w_t1, b_t1, w_t2, b_t2, out);
}

// round 12
// speedup vs baseline: 1.7631x; 1.2391x over previous
#include <cuda_runtime.h>
#include <cuda_bf16.h>
#include <math.h>
#include <stdint.h>

// Problem constants
#define Bb 16
#define Tt 16
#define Cc 64
#define HD 64
#define HW 1024
#define IMW 32

// Scratch (device globals: no allocation allowed)
__device__ float g_h   [Bb*HD*HW];
__device__ float g_hode[Bb*HD*HW];
__device__ float g_rh  [Bb*HD*HW];
__device__ float g_u   [Bb*HD*HW];
__device__ float g_gx  [(size_t)Tt*Bb*2*HD*HW];   // x-part of gates conv (+bias)
__device__ float g_cx  [(size_t)Tt*Bb*HD*HW];     // x-part of cand conv (+bias)
// Pre-split weights, bf16 bits: [hl][row][k], k = tap*64 + ci
// rows: 0 ode | 64 gates_h(128) | 192 cand_h | 256 gates_x(128) | 384 cand_x
__device__ __align__(16) unsigned short g_Bw[2][448][576];

// Smem (halves): slab 108 rc-rows (3x36) x stride 72; B 64 rows x stride 72
#define SLAB_STR 72
#define SLAB_RC  108
#define SLABH    (SLAB_RC*SLAB_STR)   // 7776
#define BSTR     72
#define BH       (64*BSTR)            // 4608
#define SMEMB    ((2*SLABH + 2*BH)*2) // 49536 bytes

// bf16 m16n8k16 MMA (standard PTX, sm_80+)
__device__ __forceinline__ void mma16816(float* c, const unsigned* a,
                                         unsigned b0, unsigned b1) {
    asm volatile(
        "mma.sync.aligned.m16n8k16.row.col.f32.bf16.bf16.f32 "
        "{%0,%1,%2,%3}, {%4,%5,%6,%7}, {%8,%9}, {%0,%1,%2,%3};\n"
        : "+f"(c[0]), "+f"(c[1]), "+f"(c[2]), "+f"(c[3])
        : "r"(a[0]), "r"(a[1]), "r"(a[2]), "r"(a[3]), "r"(b0), "r"(b1));
}
__device__ __forceinline__ void ldsm_x4(unsigned* r, uint32_t addr) {
    asm volatile("ldmatrix.sync.aligned.m8n8.x4.shared.b16 {%0,%1,%2,%3}, [%4];"
        : "=r"(r[0]), "=r"(r[1]), "=r"(r[2]), "=r"(r[3]) : "r"(addr));
}
__device__ __forceinline__ float sigmoidf_(float x) { return 1.f / (1.f + expf(-x)); }

// ===========================================================================
// Weight pre-split: fp32 -> bf16 hi/lo, layout [hl][row][tap*64+ci]
// ===========================================================================
__global__ void k_wsplit(const float* __restrict__ w_ode,
                         const float* __restrict__ w_gates,
                         const float* __restrict__ w_can)
{
    int idx = blockIdx.x*256 + threadIdx.x;     // 448*576 = 258048
    if (idx >= 448*576) return;
    int r = idx / 576, k = idx % 576;
    int tap = k >> 6, ci = k & 63;

    float v;
    if      (r < 64)  v = w_ode  [ r       *576  + ci*9      + tap];
    else if (r < 192) v = w_gates[(r-64)   *1152 + (64+ci)*9 + tap];
    else if (r < 256) v = w_can  [(r-192)  *1152 + (64+ci)*9 + tap];
    else if (r < 384) v = w_gates[(r-256)  *1152 + ci*9      + tap];
    else              v = w_can  [(r-384)  *1152 + ci*9      + tap];

    __nv_bfloat16 h = __float2bfloat16_rn(v);
    __nv_bfloat16 l = __float2bfloat16_rn(v - __bfloat162float(h));
    g_Bw[0][r][k] = __bfloat16_as_ushort(h);
    g_Bw[1][r][k] = __bfloat16_as_ushort(l);
}

// ===========================================================================
// Conv-as-GEMM. CTA (256 thr, 8 warps) computes [32 px (1 image row) x 64 oc].
// Warp w: m-half mt=w>>2 (16 px), oc-quarter nq=w&3 (16 oc).
// grid = (32 rows, nimg, nhalf). MODE: 0=ODE 1=GATES 2=CAND 3=PRE_G 4=PRE_C
// B staged per tap with register double-buffer prefetch.
// ===========================================================================
template<int MODE>
__global__ void __launch_bounds__(256) k_conv(
    const float* __restrict__ x0, const float* __restrict__ ts,
    const float* __restrict__ mask, const float* __restrict__ b_ode,
    const float* __restrict__ b_gates, const float* __restrict__ b_can,
    int step)
{
    extern __shared__ unsigned short sm2[];
    unsigned short* slab_hi = sm2;
    unsigned short* slab_lo = sm2 + SLABH;
    unsigned short* Bs_hi   = sm2 + 2*SLABH;
    unsigned short* Bs_lo   = sm2 + 2*SLABH + BH;

    const int tid  = threadIdx.x;
    const int w    = tid >> 5, lane = tid & 31;
    const int mt   = w >> 2, nq = w & 3;
    const int tile = blockIdx.x;        // image row
    const int img  = blockIdx.y;
    const int nh   = blockIdx.z;

    const float* in;
    if (MODE >= 3) {
        int t = img >> 4, b = img & 15;
        in = x0 + ((size_t)(b*Tt + (Tt-1-t))*Cc)*HW;
    } else {
        in = (MODE == 0 ? g_h : (MODE == 1 ? g_hode : g_rh)) + (size_t)img*HD*HW;
    }
    const int rowoff = (MODE == 0) ? 0
                     : (MODE == 1) ? 64 + nh*64
                     : (MODE == 2) ? 192
                     : (MODE == 3) ? 256 + nh*64
                     : 384;

    // ---- Build slabs: image rows tile-1 .. tile+1, cols -1..34 ----
    for (int i = tid; i < SLAB_RC*64; i += 256) {
        int ci = i / SLAB_RC, rc = i - ci*SLAB_RC;
        int rr = rc / 36, cc = rc - rr*36;
        int ir = tile + rr - 1, ic = cc - 1;
        float v = 0.f;
        if ((unsigned)ir < 32u && (unsigned)ic < 32u)
            v = in[ci*HW + ir*IMW + ic];
        __nv_bfloat16 h = __float2bfloat16_rn(v);
        __nv_bfloat16 l = __float2bfloat16_rn(v - __bfloat162float(h));
        slab_hi[rc*SLAB_STR + ci] = __bfloat16_as_ushort(h);
        slab_lo[rc*SLAB_STR + ci] = __bfloat16_as_ushort(l);
    }

    const uint32_t slab_hi_u = (uint32_t)__cvta_generic_to_shared(slab_hi);
    const uint32_t slab_lo_u = (uint32_t)__cvta_generic_to_shared(slab_lo);
    const uint32_t bs_hi_u   = (uint32_t)__cvta_generic_to_shared(Bs_hi);
    const uint32_t bs_lo_u   = (uint32_t)__cvta_generic_to_shared(Bs_lo);

    float acc[2][4];
    #pragma unroll
    for (int nt = 0; nt < 2; nt++)
        #pragma unroll
        for (int e = 0; e < 4; e++) acc[nt][e] = 0.f;

    // B fragment smem byte offset (16 oc rows for this warp's quarter)
    const uint32_t bfrag0 = (uint32_t)((nq*16 + (lane & 7) + ((lane >> 4) << 3))*BSTR*2)
                          + (((lane >> 3) & 1) << 4);

    // B register prefetch: thread covers rows n = tid>>3 and (tid+256)>>3
    const int bn0 = tid >> 3,        bq0 = tid & 7;
    const int bn1 = (tid + 256) >> 3, bq1 = tid & 7;
    uint4 rh[2], rl[2];
    {
        rh[0] = *(reinterpret_cast<const uint4*>(&g_Bw[0][rowoff + bn0][0]) + bq0);
        rl[0] = *(reinterpret_cast<const uint4*>(&g_Bw[1][rowoff + bn0][0]) + bq0);
        rh[1] = *(reinterpret_cast<const uint4*>(&g_Bw[0][rowoff + bn1][0]) + bq1);
        rl[1] = *(reinterpret_cast<const uint4*>(&g_Bw[1][rowoff + bn1][0]) + bq1);
    }

    #pragma unroll 1
    for (int tap = 0; tap < 9; tap++) {
        __syncthreads();   // prior-tap B reads done (tap0: slab stores issued)
        *reinterpret_cast<uint4*>(reinterpret_cast<char*>(Bs_hi) + bn0*(BSTR*2) + bq0*16) = rh[0];
        *reinterpret_cast<uint4*>(reinterpret_cast<char*>(Bs_lo) + bn0*(BSTR*2) + bq0*16) = rl[0];
        *reinterpret_cast<uint4*>(reinterpret_cast<char*>(Bs_hi) + bn1*(BSTR*2) + bq1*16) = rh[1];
        *reinterpret_cast<uint4*>(reinterpret_cast<char*>(Bs_lo) + bn1*(BSTR*2) + bq1*16) = rl[1];
        __syncthreads();
        if (tap < 8) {
            const int t1 = (tap + 1)*64;
            rh[0] = *(reinterpret_cast<const uint4*>(&g_Bw[0][rowoff + bn0][t1]) + bq0);
            rl[0] = *(reinterpret_cast<const uint4*>(&g_Bw[1][rowoff + bn0][t1]) + bq0);
            rh[1] = *(reinterpret_cast<const uint4*>(&g_Bw[0][rowoff + bn1][t1]) + bq1);
            rl[1] = *(reinterpret_cast<const uint4*>(&g_Bw[1][rowoff + bn1][t1]) + bq1);
        }

        const int tr = tap/3, tc = tap - tr*3;
        const int base_rc = tr*36 + tc + mt*16;
        const uint32_t a_off = (uint32_t)((base_rc + (lane & 15))*SLAB_STR*2)
                             + ((lane >> 4) << 4);

        #pragma unroll
        for (int kq = 0; kq < 4; kq++) {
            unsigned ah[4], al[4], bh[4], bl[4];
            ldsm_x4(ah, slab_hi_u + a_off + kq*32);
            ldsm_x4(al, slab_lo_u + a_off + kq*32);
            ldsm_x4(bh, bs_hi_u + bfrag0 + kq*32);
            ldsm_x4(bl, bs_lo_u + bfrag0 + kq*32);
            mma16816(acc[0], ah, bh[0], bh[1]);
            mma16816(acc[0], al, bh[0], bh[1]);
            mma16816(acc[0], ah, bl[0], bl[1]);
            mma16816(acc[1], ah, bh[2], bh[3]);
            mma16816(acc[1], al, bh[2], bh[3]);
            mma16816(acc[1], ah, bl[2], bl[3]);
        }
    }

    // ---- Epilogue: thread owns 8 (px, oc) values ----
    float dt = 0.f, m = 0.f;
    if (MODE == 0) dt = (step == 0) ? -0.01f : (ts[Tt-1-step] - ts[Tt-step]);
    if (MODE == 2) m  = mask[img*Tt + (Tt-1-step)];

    #pragma unroll
    for (int nt = 0; nt < 2; nt++) {
        #pragma unroll
        for (int e = 0; e < 4; e++) {
            const int c  = mt*16 + (lane >> 2) + (e >> 1)*8;
            const int oc = nq*16 + nt*8 + (lane & 3)*2 + (e & 1);
            const int px = tile*IMW + c;
            float v = acc[nt][e];
            if (MODE == 0) {
                size_t ib = (size_t)img*HD*HW + (size_t)oc*HW + px;
                g_hode[ib] = g_h[ib] + tanhf(v + b_ode[oc])*dt;
            } else if (MODE == 1) {
                float gx = g_gx[((size_t)(step*Bb + img)*(2*HD) + nh*64 + oc)*HW + px];
                float g = sigmoidf_(v + gx);
                size_t ib = (size_t)img*HD*HW + (size_t)oc*HW + px;
                if (nh == 0) g_rh[ib] = g * g_hode[ib];
                else         g_u[ib]  = g;
            } else if (MODE == 2) {
                float cx = g_cx[((size_t)(step*Bb + img)*HD + oc)*HW + px];
                size_t ib = (size_t)img*HD*HW + (size_t)oc*HW + px;
                float ho = g_hode[ib];
                g_h[ib] = ho + m*g_u[ib]*(tanhf(v + cx) - ho);
            } else if (MODE == 3) {
                g_gx[((size_t)img*(2*HD) + nh*64 + oc)*HW + px] = v + b_gates[nh*64 + oc];
            } else {
                g_cx[((size_t)img*HD + oc)*HW + px] = v + b_can[oc];
            }
        }
    }
}

// ===========================================================================
// Head: z1 = relu(W1 h + b1); z2 = W2 z1 + b2; out = [z2[:64] ; |z2[64:]|]
// ===========================================================================
__global__ void __launch_bounds__(256) k_final(
    const float* __restrict__ w1, const float* __restrict__ b1,
    const float* __restrict__ w2, const float* __restrict__ b2,
    float* __restrict__ out)
{
    extern __shared__ float smemf[];
    float* w1s = smemf;          // [64][64]
    float* w2s = smemf + 4096;   // [128][64]
    const int tid = threadIdx.x, pb = blockIdx.x, b = blockIdx.y;
    for (int i = tid; i < 4096; i += 256) w1s[i] = w1[i];
    for (int i = tid; i < 8192; i += 256) w2s[i] = w2[i];
    __syncthreads();

    const int pix = pb*256 + tid;
    float z1[64];
    #pragma unroll
    for (int co = 0; co < 64; co++) z1[co] = b1[co];
    for (int ci = 0; ci < 64; ci++) {
        float hv = g_h[((size_t)b*HD + ci)*HW + pix];
        #pragma unroll
        for (int co = 0; co < 64; co++) z1[co] += w1s[co*64 + ci]*hv;
    }
    #pragma unroll
    for (int co = 0; co < 64; co++) z1[co] = fmaxf(z1[co], 0.f);

    for (int co2 = 0; co2 < 128; co2++) {
        float a = b2[co2];
        #pragma unroll
        for (int ci = 0; ci < 64; ci++) a += w2s[co2*64 + ci]*z1[ci];
        if (co2 < 64)
            out[((size_t)b*HD + co2)*HW + pix] = a;
        else
            out[(size_t)Bb*HD*HW + ((size_t)b*HD + (co2 - 64))*HW + pix] = fabsf(a);
    }
}

// ---------------------------------------------------------------------------
extern "C" void kernel_launch(void* const* d_in, const int* in_sizes, int n_in,
                              void* d_out, int out_size)
{
    const float* input   = (const float*)d_in[0];
    const float* ts      = (const float*)d_in[1];
    const float* mask    = (const float*)d_in[2];
    const float* w_gates = (const float*)d_in[3];
    const float* b_gates = (const float*)d_in[4];
    const float* w_can   = (const float*)d_in[5];
    const float* b_can   = (const float*)d_in[6];
    const float* w_ode   = (const float*)d_in[7];
    const float* b_ode   = (const float*)d_in[8];
    const float* w_t1    = (const float*)d_in[9];
    const float* b_t1    = (const float*)d_in[10];
    const float* w_t2    = (const float*)d_in[11];
    const float* b_t2    = (const float*)d_in[12];
    float* out = (float*)d_out;

    float* hptr;
    cudaGetSymbolAddress((void**)&hptr, g_h);

    cudaFuncSetAttribute(k_conv<0>, cudaFuncAttributeMaxDynamicSharedMemorySize, SMEMB);
    cudaFuncSetAttribute(k_conv<1>, cudaFuncAttributeMaxDynamicSharedMemorySize, SMEMB);
    cudaFuncSetAttribute(k_conv<2>, cudaFuncAttributeMaxDynamicSharedMemorySize, SMEMB);
    cudaFuncSetAttribute(k_conv<3>, cudaFuncAttributeMaxDynamicSharedMemorySize, SMEMB);
    cudaFuncSetAttribute(k_conv<4>, cudaFuncAttributeMaxDynamicSharedMemorySize, SMEMB);

    cudaMemsetAsync(hptr, 0, (size_t)Bb*HD*HW*sizeof(float));
    k_wsplit<<<1008, 256>>>(w_ode, w_gates, w_can);

    // Precompute x-contributions for all T steps
    k_conv<3><<<dim3(32, Tt*Bb, 2), 256, SMEMB>>>(input, ts, mask, b_ode, b_gates, b_can, 0);
    k_conv<4><<<dim3(32, Tt*Bb, 1), 256, SMEMB>>>(input, ts, mask, b_ode, b_gates, b_can, 0);

    // Sequential scan
    for (int s = 0; s < Tt; s++) {
        k_conv<0><<<dim3(32, Bb, 1), 256, SMEMB>>>(input, ts, mask, b_ode, b_gates, b_can, s);
        k_conv<1><<<dim3(32, Bb, 2), 256, SMEMB>>>(input, ts, mask, b_ode, b_gates, b_can, s);
        k_conv<2><<<dim3(32, Bb, 1), 256, SMEMB>>>(input, ts, mask, b_ode, b_gates, b_can, s);
    }

    k_final<<<dim3(4, Bb), 256, 12288*(int)sizeof(float)>>>(w_t1, b_t1, w_t2, b_t2, out);
}

// round 13
// speedup vs baseline: 1.9367x; 1.0985x over previous
#include <cuda_runtime.h>
#include <cuda_bf16.h>
#include <math.h>
#include <stdint.h>

// Problem constants
#define Bb 16
#define Tt 16
#define Cc 64
#define HD 64
#define HW 1024
#define IMW 32

// Scratch (device globals: no allocation allowed)
__device__ float g_h   [Bb*HD*HW];
__device__ float g_hode[Bb*HD*HW];
__device__ float g_rh  [Bb*HD*HW];
__device__ float g_u   [Bb*HD*HW];
__device__ float g_gx  [(size_t)Tt*Bb*2*HD*HW];   // x-part of gates conv (+bias)
__device__ float g_cx  [(size_t)Tt*Bb*HD*HW];     // x-part of cand conv (+bias)
// Pre-split weights, bf16 bits: [hl][row][k], k = tap*64 + ci
// rows: 0 ode | 64 gates_h(128) | 192 cand_h | 256 gates_x(128) | 384 cand_x
__device__ __align__(16) unsigned short g_Bw[2][448][576];

// Smem (halves): slab 108 rc-rows (3x36) x stride 72; B 64 rows x stride 72
#define SLAB_STR 72
#define SLAB_RC  108
#define SLABH    (SLAB_RC*SLAB_STR)   // 7776
#define BSTR     72
#define BH       (64*BSTR)            // 4608
#define SMEMB    ((2*SLABH + 2*BH)*2) // 49536 bytes

// bf16 m16n8k16 MMA (standard PTX, sm_80+)
__device__ __forceinline__ void mma16816(float* c, const unsigned* a,
                                         unsigned b0, unsigned b1) {
    asm volatile(
        "mma.sync.aligned.m16n8k16.row.col.f32.bf16.bf16.f32 "
        "{%0,%1,%2,%3}, {%4,%5,%6,%7}, {%8,%9}, {%0,%1,%2,%3};\n"
        : "+f"(c[0]), "+f"(c[1]), "+f"(c[2]), "+f"(c[3])
        : "r"(a[0]), "r"(a[1]), "r"(a[2]), "r"(a[3]), "r"(b0), "r"(b1));
}
__device__ __forceinline__ void ldsm_x4(unsigned* r, uint32_t addr) {
    asm volatile("ldmatrix.sync.aligned.m8n8.x4.shared.b16 {%0,%1,%2,%3}, [%4];"
        : "=r"(r[0]), "=r"(r[1]), "=r"(r[2]), "=r"(r[3]) : "r"(addr));
}
__device__ __forceinline__ float sigmoidf_(float x) { return 1.f / (1.f + expf(-x)); }

// ===========================================================================
// Weight pre-split: fp32 -> bf16 hi/lo, layout [hl][row][tap*64+ci]
// ===========================================================================
__global__ void k_wsplit(const float* __restrict__ w_ode,
                         const float* __restrict__ w_gates,
                         const float* __restrict__ w_can)
{
    int idx = blockIdx.x*256 + threadIdx.x;     // 448*576 = 258048
    if (idx >= 448*576) return;
    int r = idx / 576, k = idx % 576;
    int tap = k >> 6, ci = k & 63;

    float v;
    if      (r < 64)  v = w_ode  [ r       *576  + ci*9      + tap];
    else if (r < 192) v = w_gates[(r-64)   *1152 + (64+ci)*9 + tap];
    else if (r < 256) v = w_can  [(r-192)  *1152 + (64+ci)*9 + tap];
    else if (r < 384) v = w_gates[(r-256)  *1152 + ci*9      + tap];
    else              v = w_can  [(r-384)  *1152 + ci*9      + tap];

    __nv_bfloat16 h = __float2bfloat16_rn(v);
    __nv_bfloat16 l = __float2bfloat16_rn(v - __bfloat162float(h));
    g_Bw[0][r][k] = __bfloat16_as_ushort(h);
    g_Bw[1][r][k] = __bfloat16_as_ushort(l);
}

// ===========================================================================
// Conv-as-GEMM with UNIT FUSION. CTA (256 thr, 8 warps) owns one image row
// (32 px) and runs NU sequential [32px x 64oc] conv-units over the SAME slab.
// MODE: 0=ODE(1u) 1=GATES(2u: reset,update) 2=CAND(1u) 3=PRE(3u: gx0,gx1,cx)
// grid = (32 rows, nimg). Warp w: mt=w>>2 (16px half), nq=w&3 (16oc quarter).
// ===========================================================================
template<int MODE>
__global__ void __launch_bounds__(256) k_conv(
    const float* __restrict__ x0, const float* __restrict__ ts,
    const float* __restrict__ mask, const float* __restrict__ b_ode,
    const float* __restrict__ b_gates, const float* __restrict__ b_can,
    int step)
{
    constexpr int NU = (MODE == 1) ? 2 : (MODE == 3) ? 3 : 1;

    extern __shared__ unsigned short sm2[];
    unsigned short* slab_hi = sm2;
    unsigned short* slab_lo = sm2 + SLABH;
    unsigned short* Bs_hi   = sm2 + 2*SLABH;
    unsigned short* Bs_lo   = sm2 + 2*SLABH + BH;

    const int tid  = threadIdx.x;
    const int w    = tid >> 5, lane = tid & 31;
    const int mt   = w >> 2, nq = w & 3;
    const int tile = blockIdx.x;        // image row
    const int img  = blockIdx.y;

    const float* in;
    if (MODE == 3) {
        int t = img >> 4, b = img & 15;
        in = x0 + ((size_t)(b*Tt + (Tt-1-t))*Cc)*HW;
    } else {
        in = (MODE == 0 ? g_h : (MODE == 1 ? g_hode : g_rh)) + (size_t)img*HD*HW;
    }

    // compile-time row offsets per unit
    auto ROWOFF = [](int u) {
        return (MODE == 0) ? 0
             : (MODE == 1) ? 64 + u*64
             : (MODE == 2) ? 192
             : (u == 2 ? 384 : 256 + u*64);
    };

    // ---- Build slabs: image rows tile-1 .. tile+1, cols -1..34 ----
    for (int i = tid; i < SLAB_RC*64; i += 256) {
        int ci = i / SLAB_RC, rc = i - ci*SLAB_RC;
        int rr = rc / 36, cc = rc - rr*36;
        int ir = tile + rr - 1, ic = cc - 1;
        float v = 0.f;
        if ((unsigned)ir < 32u && (unsigned)ic < 32u)
            v = in[ci*HW + ir*IMW + ic];
        __nv_bfloat16 h = __float2bfloat16_rn(v);
        __nv_bfloat16 l = __float2bfloat16_rn(v - __bfloat162float(h));
        slab_hi[rc*SLAB_STR + ci] = __bfloat16_as_ushort(h);
        slab_lo[rc*SLAB_STR + ci] = __bfloat16_as_ushort(l);
    }

    const uint32_t slab_hi_u = (uint32_t)__cvta_generic_to_shared(slab_hi);
    const uint32_t slab_lo_u = (uint32_t)__cvta_generic_to_shared(slab_lo);
    const uint32_t bs_hi_u   = (uint32_t)__cvta_generic_to_shared(Bs_hi);
    const uint32_t bs_lo_u   = (uint32_t)__cvta_generic_to_shared(Bs_lo);

    // B fragment smem byte offset (16 oc rows for this warp's quarter)
    const uint32_t bfrag0 = (uint32_t)((nq*16 + (lane & 7) + ((lane >> 4) << 3))*BSTR*2)
                          + (((lane >> 3) & 1) << 4);

    // B register prefetch: thread covers rows n = tid>>3 and (tid+256)>>3
    const int bn0 = tid >> 3,         bq0 = tid & 7;
    const int bn1 = (tid + 256) >> 3, bq1 = tid & 7;
    uint4 rh[2], rl[2];
    rh[0] = *(reinterpret_cast<const uint4*>(&g_Bw[0][ROWOFF(0) + bn0][0]) + bq0);
    rl[0] = *(reinterpret_cast<const uint4*>(&g_Bw[1][ROWOFF(0) + bn0][0]) + bq0);
    rh[1] = *(reinterpret_cast<const uint4*>(&g_Bw[0][ROWOFF(0) + bn1][0]) + bq1);
    rl[1] = *(reinterpret_cast<const uint4*>(&g_Bw[1][ROWOFF(0) + bn1][0]) + bq1);

    // epilogue constants
    float dt = 0.f, m = 0.f;
    if (MODE == 0) dt = (step == 0) ? -0.01f : (ts[Tt-1-step] - ts[Tt-step]);
    if (MODE == 2) m  = mask[img*Tt + (Tt-1-step)];

    #pragma unroll
    for (int u = 0; u < NU; u++) {
        float acc[2][4];
        #pragma unroll
        for (int nt = 0; nt < 2; nt++)
            #pragma unroll
            for (int e = 0; e < 4; e++) acc[nt][e] = 0.f;

        #pragma unroll 1
        for (int tap = 0; tap < 9; tap++) {
            __syncthreads();   // prior reads of Bs done (tap0/u0: slab stores issued)
            *reinterpret_cast<uint4*>(reinterpret_cast<char*>(Bs_hi) + bn0*(BSTR*2) + bq0*16) = rh[0];
            *reinterpret_cast<uint4*>(reinterpret_cast<char*>(Bs_lo) + bn0*(BSTR*2) + bq0*16) = rl[0];
            *reinterpret_cast<uint4*>(reinterpret_cast<char*>(Bs_hi) + bn1*(BSTR*2) + bq1*16) = rh[1];
            *reinterpret_cast<uint4*>(reinterpret_cast<char*>(Bs_lo) + bn1*(BSTR*2) + bq1*16) = rl[1];
            __syncthreads();

            // prefetch next (tap+1, or next unit's tap 0)
            {
                const bool wrap = (tap == 8);
                const bool valid = !wrap || (u + 1 < NU);
                if (valid) {
                    const int ro = wrap ? ROWOFF(u + 1 < NU ? u + 1 : u) : ROWOFF(u);
                    const int t1 = wrap ? 0 : (tap + 1)*64;
                    rh[0] = *(reinterpret_cast<const uint4*>(&g_Bw[0][ro + bn0][t1]) + bq0);
                    rl[0] = *(reinterpret_cast<const uint4*>(&g_Bw[1][ro + bn0][t1]) + bq0);
                    rh[1] = *(reinterpret_cast<const uint4*>(&g_Bw[0][ro + bn1][t1]) + bq1);
                    rl[1] = *(reinterpret_cast<const uint4*>(&g_Bw[1][ro + bn1][t1]) + bq1);
                }
            }

            const int tr = tap/3, tc = tap - tr*3;
            const int base_rc = tr*36 + tc + mt*16;
            const uint32_t a_off = (uint32_t)((base_rc + (lane & 15))*SLAB_STR*2)
                                 + ((lane >> 4) << 4);

            #pragma unroll
            for (int kq = 0; kq < 4; kq++) {
                unsigned ah[4], bh[4];
                ldsm_x4(ah, slab_hi_u + a_off + kq*32);
                ldsm_x4(bh, bs_hi_u + bfrag0 + kq*32);
                mma16816(acc[0], ah, bh[0], bh[1]);
                mma16816(acc[1], ah, bh[2], bh[3]);
                unsigned al[4];
                ldsm_x4(al, slab_lo_u + a_off + kq*32);
                mma16816(acc[0], al, bh[0], bh[1]);
                mma16816(acc[1], al, bh[2], bh[3]);
                unsigned bl[4];
                ldsm_x4(bl, bs_lo_u + bfrag0 + kq*32);
                mma16816(acc[0], ah, bl[0], bl[1]);
                mma16816(acc[1], ah, bl[2], bl[3]);
            }
        }

        // ---- Epilogue for unit u: thread owns 8 (px, oc) values ----
        #pragma unroll
        for (int nt = 0; nt < 2; nt++) {
            #pragma unroll
            for (int e = 0; e < 4; e++) {
                const int c  = mt*16 + (lane >> 2) + (e >> 1)*8;
                const int oc = nq*16 + nt*8 + (lane & 3)*2 + (e & 1);
                const int px = tile*IMW + c;
                float v = acc[nt][e];
                if (MODE == 0) {
                    size_t ib = (size_t)img*HD*HW + (size_t)oc*HW + px;
                    g_hode[ib] = g_h[ib] + tanhf(v + b_ode[oc])*dt;
                } else if (MODE == 1) {
                    float gx = g_gx[((size_t)(step*Bb + img)*(2*HD) + u*64 + oc)*HW + px];
                    float g = sigmoidf_(v + gx);
                    size_t ib = (size_t)img*HD*HW + (size_t)oc*HW + px;
                    if (u == 0) g_rh[ib] = g * g_hode[ib];
                    else        g_u[ib]  = g;
                } else if (MODE == 2) {
                    float cx = g_cx[((size_t)(step*Bb + img)*HD + oc)*HW + px];
                    size_t ib = (size_t)img*HD*HW + (size_t)oc*HW + px;
                    float ho = g_hode[ib];
                    g_h[ib] = ho + m*g_u[ib]*(tanhf(v + cx) - ho);
                } else {
                    if (u < 2)
                        g_gx[((size_t)img*(2*HD) + u*64 + oc)*HW + px] = v + b_gates[u*64 + oc];
                    else
                        g_cx[((size_t)img*HD + oc)*HW + px] = v + b_can[oc];
                }
            }
        }
    }
}

// ===========================================================================
// Head: z1 = relu(W1 h + b1); z2 = W2 z1 + b2; out = [z2[:64] ; |z2[64:]|]
// ===========================================================================
__global__ void __launch_bounds__(256) k_final(
    const float* __restrict__ w1, const float* __restrict__ b1,
    const float* __restrict__ w2, const float* __restrict__ b2,
    float* __restrict__ out)
{
    extern __shared__ float smemf[];
    float* w1s = smemf;          // [64][64]
    float* w2s = smemf + 4096;   // [128][64]
    const int tid = threadIdx.x, pb = blockIdx.x, b = blockIdx.y;
    for (int i = tid; i < 4096; i += 256) w1s[i] = w1[i];
    for (int i = tid; i < 8192; i += 256) w2s[i] = w2[i];
    __syncthreads();

    const int pix = pb*256 + tid;
    float z1[64];
    #pragma unroll
    for (int co = 0; co < 64; co++) z1[co] = b1[co];
    for (int ci = 0; ci < 64; ci++) {
        float hv = g_h[((size_t)b*HD + ci)*HW + pix];
        #pragma unroll
        for (int co = 0; co < 64; co++) z1[co] += w1s[co*64 + ci]*hv;
    }
    #pragma unroll
    for (int co = 0; co < 64; co++) z1[co] = fmaxf(z1[co], 0.f);

    for (int co2 = 0; co2 < 128; co2++) {
        float a = b2[co2];
        #pragma unroll
        for (int ci = 0; ci < 64; ci++) a += w2s[co2*64 + ci]*z1[ci];
        if (co2 < 64)
            out[((size_t)b*HD + co2)*HW + pix] = a;
        else
            out[(size_t)Bb*HD*HW + ((size_t)b*HD + (co2 - 64))*HW + pix] = fabsf(a);
    }
}

// ---------------------------------------------------------------------------
extern "C" void kernel_launch(void* const* d_in, const int* in_sizes, int n_in,
                              void* d_out, int out_size)
{
    const float* input   = (const float*)d_in[0];
    const float* ts      = (const float*)d_in[1];
    const float* mask    = (const float*)d_in[2];
    const float* w_gates = (const float*)d_in[3];
    const float* b_gates = (const float*)d_in[4];
    const float* w_can   = (const float*)d_in[5];
    const float* b_can   = (const float*)d_in[6];
    const float* w_ode   = (const float*)d_in[7];
    const float* b_ode   = (const float*)d_in[8];
    const float* w_t1    = (const float*)d_in[9];
    const float* b_t1    = (const float*)d_in[10];
    const float* w_t2    = (const float*)d_in[11];
    const float* b_t2    = (const float*)d_in[12];
    float* out = (float*)d_out;

    float* hptr;
    cudaGetSymbolAddress((void**)&hptr, g_h);

    cudaFuncSetAttribute(k_conv<0>, cudaFuncAttributeMaxDynamicSharedMemorySize, SMEMB);
    cudaFuncSetAttribute(k_conv<1>, cudaFuncAttributeMaxDynamicSharedMemorySize, SMEMB);
    cudaFuncSetAttribute(k_conv<2>, cudaFuncAttributeMaxDynamicSharedMemorySize, SMEMB);
    cudaFuncSetAttribute(k_conv<3>, cudaFuncAttributeMaxDynamicSharedMemorySize, SMEMB);

    cudaMemsetAsync(hptr, 0, (size_t)Bb*HD*HW*sizeof(float));
    k_wsplit<<<1008, 256>>>(w_ode, w_gates, w_can);

    // Precompute x-contributions for all T steps (fused: gx0, gx1, cx per CTA)
    k_conv<3><<<dim3(32, Tt*Bb), 256, SMEMB>>>(input, ts, mask, b_ode, b_gates, b_can, 0);

    // Sequential scan (gates fused: reset+update per CTA)
    for (int s = 0; s < Tt; s++) {
        k_conv<0><<<dim3(32, Bb), 256, SMEMB>>>(input, ts, mask, b_ode, b_gates, b_can, s);
        k_conv<1><<<dim3(32, Bb), 256, SMEMB>>>(input, ts, mask, b_ode, b_gates, b_can, s);
        k_conv<2><<<dim3(32, Bb), 256, SMEMB>>>(input, ts, mask, b_ode, b_gates, b_can, s);
    }

    k_final<<<dim3(4, Bb), 256, 12288*(int)sizeof(float)>>>(w_t1, b_t1, w_t2, b_t2, out);
}